// round 15
// baseline (speedup 1.0000x reference)
#include <cuda_runtime.h>
#include <cstdint>
#include <cstddef>

#define BATCH 4
#define SEQ 2048
#define DMODEL 384
#define NHEADS 6
#define HD 64
#define BH (BATCH*NHEADS)      /* 24 */

// ---------------- scratch (static device arrays; no cudaMalloc allowed) -------
__device__ __align__(16) int8_t g_Q  [(size_t)BH*SEQ*HD];        // [bh][n][d]
__device__ __align__(16) int8_t g_K  [(size_t)BH*SEQ*HD];        // [bh][n][d]
// V packed words: word (bh, nblk, d) = V[nblk*4 .. +3][d] bytes (packed along n)
__device__ __align__(16) int8_t g_Vp [(size_t)BH*(SEQ/4)*HD*4];  // [bh][nblk 512][d 64]
__device__ __align__(16) int8_t g_ctx[(size_t)BATCH*SEQ*DMODEL]; // [b][n][h*hd]

__device__ __forceinline__ int dp4a_us(unsigned a, int b, int c) {
    int d;
    asm("dp4a.u32.s32 %0, %1, %2, %3;" : "=r"(d) : "r"(a), "r"(b), "r"(c));
    return d;
}
__device__ __forceinline__ void ffma2(unsigned long long& d,
                                      unsigned long long a, unsigned long long b) {
    asm("fma.rn.f32x2 %0, %1, %2, %0;" : "+l"(d) : "l"(a), "l"(b));
}
__device__ __forceinline__ unsigned long long pack2(float lo, float hi) {
    unsigned long long p;
    asm("mov.b64 %0, {%1, %2};" : "=l"(p) : "f"(lo), "f"(hi));
    return p;
}
__device__ __forceinline__ void unpack2(unsigned long long p, float& lo, float& hi) {
    asm("mov.b64 {%0, %1}, %2;" : "=f"(lo), "=f"(hi) : "l"(p));
}
__device__ __forceinline__ int clamp_i8(int v) {
    return v < -128 ? -128 : (v > 127 ? 127 : v);
}
__device__ __forceinline__ unsigned pack_bytes(int v0, int v1, int v2, int v3) {
    return  ((unsigned)(unsigned char)(int8_t)v0)
          | (((unsigned)(unsigned char)(int8_t)v1) << 8)
          | (((unsigned)(unsigned char)(int8_t)v2) << 16)
          | (((unsigned)(unsigned char)(int8_t)v3) << 24);
}

// ---------------------------------------------------------------------------
// Kernel 1: QKV projection (f32x2 FMA, double-buffered, vectorized prefetch).
// Identical to R12 (verified 128us, rel_err 0). K in normal [bh][n][d] layout.
// ---------------------------------------------------------------------------
__global__ void __launch_bounds__(256, 2) proj_kernel(
    const float* __restrict__ x,
    const float* __restrict__ wq, const float* __restrict__ bq,
    const float* __restrict__ wk, const float* __restrict__ bk,
    const float* __restrict__ wv, const float* __restrict__ bv)
{
    __shared__ float xs[2][16][132];   // [buf][kk][m]
    __shared__ float ws[2][16][132];   // [buf][kk][n]
    __shared__ int8_t vq[128][132];    // V transpose staging (z==2)

    const int z = blockIdx.z;
    const float* w    = (z == 0) ? wq : ((z == 1) ? wk : wv);
    const float* bias = (z == 0) ? bq : ((z == 1) ? bk : bv);
    const int m0 = blockIdx.x * 128;
    const int n0 = blockIdx.y * 128;
    const int tid = threadIdx.x, tx = tid & 15, ty = tid >> 4;
    const int r0s = tid >> 2;
    const int c4s = tid & 3;

    unsigned long long acc[4][8];
    #pragma unroll
    for (int i = 0; i < 4; i++)
        #pragma unroll
        for (int j = 0; j < 8; j++) acc[i][j] = 0ULL;

    float4 px[2], pw[2];
    #pragma unroll
    for (int it = 0; it < 2; it++) {
        int row = r0s + it * 64;
        px[it] = *(const float4*)&x[(size_t)(m0 + row) * DMODEL + c4s * 4];
        pw[it] = *(const float4*)&w[(size_t)(n0 + row) * DMODEL + c4s * 4];
    }
    #pragma unroll
    for (int it = 0; it < 2; it++) {
        int row = r0s + it * 64;
        xs[0][c4s*4+0][row] = px[it].x; xs[0][c4s*4+1][row] = px[it].y;
        xs[0][c4s*4+2][row] = px[it].z; xs[0][c4s*4+3][row] = px[it].w;
        ws[0][c4s*4+0][row] = pw[it].x; ws[0][c4s*4+1][row] = pw[it].y;
        ws[0][c4s*4+2][row] = pw[it].z; ws[0][c4s*4+3][row] = pw[it].w;
    }
    __syncthreads();

    for (int kc = 0; kc < 24; kc++) {
        const int cur = kc & 1;
        if (kc + 1 < 24) {
            int k0 = (kc + 1) * 16;
            #pragma unroll
            for (int it = 0; it < 2; it++) {
                int row = r0s + it * 64;
                px[it] = *(const float4*)&x[(size_t)(m0 + row) * DMODEL + k0 + c4s * 4];
                pw[it] = *(const float4*)&w[(size_t)(n0 + row) * DMODEL + k0 + c4s * 4];
            }
        }
        #pragma unroll
        for (int kk = 0; kk < 16; kk++) {
            ulonglong2 a01 = *(ulonglong2*)&xs[cur][kk][ty * 8];
            ulonglong2 a23 = *(ulonglong2*)&xs[cur][kk][ty * 8 + 4];
            float4 bA = *(float4*)&ws[cur][kk][tx * 4];
            float4 bB = *(float4*)&ws[cur][kk][64 + tx * 4];
            unsigned long long a[4] = {a01.x, a01.y, a23.x, a23.y};
            unsigned long long bd[8];
            bd[0] = pack2(bA.x, bA.x); bd[1] = pack2(bA.y, bA.y);
            bd[2] = pack2(bA.z, bA.z); bd[3] = pack2(bA.w, bA.w);
            bd[4] = pack2(bB.x, bB.x); bd[5] = pack2(bB.y, bB.y);
            bd[6] = pack2(bB.z, bB.z); bd[7] = pack2(bB.w, bB.w);
            #pragma unroll
            for (int i = 0; i < 4; i++)
                #pragma unroll
                for (int j = 0; j < 8; j++)
                    ffma2(acc[i][j], a[i], bd[j]);
        }
        if (kc + 1 < 24) {
            const int nb = (kc + 1) & 1;
            #pragma unroll
            for (int it = 0; it < 2; it++) {
                int row = r0s + it * 64;
                xs[nb][c4s*4+0][row] = px[it].x; xs[nb][c4s*4+1][row] = px[it].y;
                xs[nb][c4s*4+2][row] = px[it].z; xs[nb][c4s*4+3][row] = px[it].w;
                ws[nb][c4s*4+0][row] = pw[it].x; ws[nb][c4s*4+1][row] = pw[it].y;
                ws[nb][c4s*4+2][row] = pw[it].z; ws[nb][c4s*4+3][row] = pw[it].w;
            }
        }
        __syncthreads();
    }

    float bb[8];
    #pragma unroll
    for (int e = 0; e < 4; e++) bb[e] = bias[n0 + tx * 4 + e];
    #pragma unroll
    for (int e = 4; e < 8; e++) bb[e] = bias[n0 + 64 + tx * 4 + (e - 4)];

    if (z < 2) {
        int8_t* dst = (z == 0) ? g_Q : g_K;
        const int hA = n0 >> 6, hB = hA + 1;
        #pragma unroll
        for (int mp = 0; mp < 4; mp++) {
            #pragma unroll
            for (int par = 0; par < 2; par++) {
                int m = m0 + ty * 8 + mp * 2 + par;
                int b_ = m >> 11, n = m & 2047;
                unsigned wA = 0, wB = 0;
                #pragma unroll
                for (int j = 0; j < 8; j++) {
                    float lo, hi; unpack2(acc[mp][j], lo, hi);
                    float v = (par == 0) ? lo : hi;
                    float r = floorf(((v + bb[j]) * 16384.0f) * (1.0f / 256.0f));
                    r = fminf(fmaxf(r, -128.0f), 127.0f);
                    unsigned u = (unsigned)(unsigned char)(int8_t)(int)r;
                    if (j < 4) wA |= u << (8 * j);
                    else       wB |= u << (8 * (j - 4));
                }
                ((int*)dst)[((size_t)(b_ * NHEADS + hA) * SEQ + n) * 16 + tx] = (int)wA;
                ((int*)dst)[((size_t)(b_ * NHEADS + hB) * SEQ + n) * 16 + tx] = (int)wB;
            }
        }
    } else {
        #pragma unroll
        for (int mp = 0; mp < 4; mp++) {
            #pragma unroll
            for (int j = 0; j < 8; j++) {
                float lo, hi; unpack2(acc[mp][j], lo, hi);
                float r0 = floorf(((lo + bb[j]) * 16384.0f) * (1.0f / 256.0f));
                r0 = fminf(fmaxf(r0, -128.0f), 127.0f);
                float r1 = floorf(((hi + bb[j]) * 16384.0f) * (1.0f / 256.0f));
                r1 = fminf(fmaxf(r1, -128.0f), 127.0f);
                int col = (j < 4) ? (tx * 4 + j) : (64 + tx * 4 + (j - 4));
                vq[col][ty * 8 + mp * 2]     = (int8_t)(int)r0;
                vq[col][ty * 8 + mp * 2 + 1] = (int8_t)(int)r1;
            }
        }
        __syncthreads();
        int b_ = m0 >> 11;
        int nloc = m0 & 2047;
        #pragma unroll
        for (int it = 0; it < 16; it++) {
            int idx = tid + it * 256;
            int col = idx & 127;
            int j4  = idx >> 7;
            int word = *(int*)&vq[col][j4 * 4];
            int cg = n0 + col, h = cg >> 6, d = cg & 63;
            size_t nblk = (size_t)((nloc >> 2) + j4);
            ((int*)g_Vp)[((size_t)(b_ * NHEADS + h) * (SEQ/4) + nblk) * HD + d] = word;
        }
    }
}

// ---------------------------------------------------------------------------
// Kernel 2: fused attention, 256 threads, 16-q strips, 3 CTAs/SM.
// Phase 1: logits (R12-verified LDG-prefetch staging) + cmax in registers
// Phase 2: merged exact ITA scan (1 pass, 16 threads) + ordered relevance lists
// Phase 3: exact sparse attn@V (only es>0 chunks; V straight from L2)
// ---------------------------------------------------------------------------
#define QROWS 16
#define SW 516                                    /* padded S row (words) */
#define QSP 20                                    /* qs row pad */
#define KP 260                                    /* K tile row pad (256 keys) */
#define UB_INTS (16*KP)                           /* one K buffer: 4160 ints */
#define U_INTS (2*UB_INTS)                        /* 8320 ints */
#define ATTN_SMEM_INTS (QROWS*SW + 16*QSP + U_INTS + 528 + 512 + 48)
#define ATTN_SMEM_BYTES (ATTN_SMEM_INTS * 4)      /* 71936 B -> 3 CTAs/SM */

extern __shared__ int smem_raw[];

__global__ void __launch_bounds__(256, 3) attn_fused()
{
    int* SM = smem_raw;
    unsigned* S = (unsigned*)SM;                  // [16][SW] logits words
    int* qs    = SM + QROWS * SW;                 // [16][QSP] transposed Q
    int* U     = qs + 16 * QSP;                   // K double-buffer
    unsigned char* cmaxA = (unsigned char*)(U + U_INTS);   // [16][132]
    unsigned char* lst   = cmaxA + 16 * 132;               // [16][128]
    int* gmaxs = (int*)(lst + 16 * 128);          // [16]
    int* invs  = gmaxs + QROWS;                   // [16]
    int* cnt   = invs + QROWS;                    // [16]

    const int bh = blockIdx.y;
    const int q0 = blockIdx.x * QROWS;
    const int tid = threadIdx.x;
    const int lane = tid & 31, warp = tid >> 5;   // 8 warps
    const int rg = warp & 3;                      // row group (rows rg*4..+3)
    const int kh = warp >> 2;                     // key half (0/1)

    const int* Qw = (const int*)g_Q + (size_t)bh * SEQ * (HD/4) + (size_t)q0 * (HD/4);
    const int* Kw = (const int*)g_K + (size_t)bh * SEQ * (HD/4);

    // ---- Q transposed: qs[kk][qrow] (256 words) ----
    qs[(tid & 15) * QSP + (tid >> 4)] = Qw[(tid >> 4) * 16 + (tid & 15)];

    // ---- stage K tile 0 (256 keys x 16 words = 4096 ints) ----
    int pre[16];
    #pragma unroll
    for (int it = 0; it < 16; it++) pre[it] = Kw[tid + it * 256];
    #pragma unroll
    for (int it = 0; it < 16; it++) {
        int idx = tid + it * 256;
        U[(idx & 15) * KP + (idx >> 4)] = pre[it];
    }
    __syncthreads();

    // -------- Phase 1: logits, 8 tiles of 256 keys, single sync/tile --------
    for (int t = 0; t < 8; t++) {
        const int cur = t & 1;
        if (t + 1 < 8) {
            const int* Kt = Kw + (size_t)(t + 1) * 4096;
            #pragma unroll
            for (int it = 0; it < 16; it++) pre[it] = Kt[tid + it * 256];
        }
        const int* kbc = U + cur * UB_INTS;
        int acc[4][4];
        #pragma unroll
        for (int i = 0; i < 4; i++)
            #pragma unroll
            for (int j = 0; j < 4; j++) acc[i][j] = 0;
        #pragma unroll
        for (int kk = 0; kk < 16; kk++) {
            int4 av = *(const int4*)&qs[kk * QSP + rg * 4];              // broadcast
            int4 bv = *(const int4*)&kbc[kk * KP + kh * 128 + lane * 4]; // CF stride 4
            int a[4] = {av.x, av.y, av.z, av.w};
            int b[4] = {bv.x, bv.y, bv.z, bv.w};
            #pragma unroll
            for (int i = 0; i < 4; i++)
                #pragma unroll
                for (int j = 0; j < 4; j++)
                    acc[i][j] = __dp4a(a[i], b[j], acc[i][j]);
        }
        const int cj = t * 16 + kh * 8 + (lane >> 2);     // chunk id of this lane group
        #pragma unroll
        for (int i = 0; i < 4; i++) {
            unsigned w0 = pack_bytes(clamp_i8((acc[i][0]*5) >> 12), clamp_i8((acc[i][1]*5) >> 12),
                                     clamp_i8((acc[i][2]*5) >> 12), clamp_i8((acc[i][3]*5) >> 12));
            S[(rg * 4 + i) * SW + t * 64 + kh * 32 + lane] = w0;
            // chunk max: 4 bytes in-thread, then across the 4 lanes of the chunk
            int m1 = __vmaxs4((int)w0, __byte_perm(w0, w0, 0x1032));
            int m2 = __vmaxs4(m1, __byte_perm(m1, m1, 0x2301));
            int cm = (int)(int8_t)(m2 & 0xFF);
            cm = max(cm, __shfl_xor_sync(0xFFFFFFFFu, cm, 1));
            cm = max(cm, __shfl_xor_sync(0xFFFFFFFFu, cm, 2));
            if ((lane & 3) == 0)
                cmaxA[(rg * 4 + i) * 132 + cj] = (unsigned char)(cm + 128);
        }
        if (t + 1 < 8) {
            const int nb = (t + 1) & 1;
            #pragma unroll
            for (int it = 0; it < 16; it++) {
                int idx = tid + it * 256;
                U[nb * UB_INTS + (idx & 15) * KP + (idx >> 4)] = pre[it];
            }
        }
        __syncthreads();
    }

    // -------- Phase 2: merged exact ITA scan (1 thread/row, 2 per warp) ------
    if ((tid & 15) == 0) {
        int row = tid >> 4;
        const unsigned char* cm = cmaxA + row * 132;
        const int* srow = (const int*)&S[row * SW];
        unsigned char* myl = lst + row * 128;
        int g = -128, ps = 0, n = 0;
        for (int j = 0; j < 128; j++) {
            int c = (int)cm[j] - 128;
            if (c > g) {
                int sh = c - g;
                ps = (sh < 31) ? (ps >> sh) : 0;
                g = c;
            }
            if (c >= g - 8) {                     // es > 0 exactly here; else es == 0
                int4 wv = *(const int4*)&srow[j * 4];
                int words[4] = {wv.x, wv.y, wv.z, wv.w};
                int es = 0;
                #pragma unroll
                for (int jw = 0; jw < 4; jw++) {
                    int wvv = words[jw];
                    #pragma unroll
                    for (int b = 0; b < 4; b++) {
                        int xv = (int)(int8_t)((unsigned)wvv >> (8 * b));
                        int df = g - xv;          // >= 0
                        es += (df < 9) ? (256 >> df) : 0;
                    }
                }
                ps += es;
                myl[n++] = (unsigned char)j;
            }
        }
        gmaxs[row] = g;
        invs[row] = 65280 / ps;                   // exact == floor(65280.0/ps)
        cnt[row] = n;
    }
    __syncthreads();

    // -------- Phase 3: EXACT SPARSE attn @ V --------
    // Warp handles 2 rows; lanes cover d (lane, lane+32). Skipped chunks are exact 0.
    {
        const int* Vg = (const int*)g_Vp + (size_t)bh * (SEQ/4) * HD;
        const int b_ = bh / NHEADS, h = bh % NHEADS;
        #pragma unroll
        for (int r = 0; r < 2; r++) {
            int row = warp * 2 + r;
            int n = cnt[row];
            int gm = gmaxs[row];
            unsigned inv = (unsigned)invs[row];
            int acc0 = 0, acc1 = 0;
            for (int ii = 0; ii < n; ii++) {
                int j = (int)lst[row * 128 + ii];                 // chunk id 0..127
                int4 lw = *(const int4*)&S[row * SW + j * 4];     // broadcast
                int lwa[4] = {lw.x, lw.y, lw.z, lw.w};
                #pragma unroll
                for (int kw = 0; kw < 4; kw++) {
                    unsigned xw = (unsigned)lwa[kw];
                    unsigned aw = 0;
                    #pragma unroll
                    for (int bb2 = 0; bb2 < 4; bb2++) {
                        int xv = (int)(int8_t)(xw >> (8 * bb2));
                        int df = gm - xv;
                        if (df > 31) df = 31;
                        aw |= (inv >> df) << (8 * bb2);
                    }
                    int base = (j * 4 + kw) * 64;                  // kword * HD
                    acc0 = dp4a_us(aw, Vg[base + lane],      acc0);
                    acc1 = dp4a_us(aw, Vg[base + 32 + lane], acc1);
                }
            }
            int q = q0 + row;
            int8_t* dst = g_ctx + ((size_t)(b_ * SEQ + q)) * DMODEL + h * HD;
            dst[lane]      = (int8_t)clamp_i8(acc0 >> 8);         // floor(acc/256)
            dst[32 + lane] = (int8_t)clamp_i8(acc1 >> 8);
        }
    }
}

// ---------------------------------------------------------------------------
// Kernel 3: out = requantize(ctx @ wo^T + bo, 256, 7), f32x2, double-buffered.
// Identical to R12 (verified).
// ---------------------------------------------------------------------------
__global__ void __launch_bounds__(256, 2) out_kernel(
    const float* __restrict__ wo, const float* __restrict__ bo,
    float* __restrict__ out)
{
    __shared__ float cs[2][16][132];
    __shared__ float ws[2][16][132];

    const int m0 = blockIdx.x * 128;
    const int n0 = blockIdx.y * 128;
    const int tid = threadIdx.x, tx = tid & 15, ty = tid >> 4;
    const int r0s = tid >> 2;
    const int c4s = tid & 3;

    unsigned long long acc[4][8];
    #pragma unroll
    for (int i = 0; i < 4; i++)
        #pragma unroll
        for (int j = 0; j < 8; j++) acc[i][j] = 0ULL;

    int pc[2]; float4 pw[2];
    #pragma unroll
    for (int it = 0; it < 2; it++) {
        int row = r0s + it * 64;
        pc[it] = *(const int*)&g_ctx[(size_t)(m0 + row) * DMODEL + c4s * 4];
        pw[it] = *(const float4*)&wo[(size_t)(n0 + row) * DMODEL + c4s * 4];
    }
    #pragma unroll
    for (int it = 0; it < 2; it++) {
        int row = r0s + it * 64;
        #pragma unroll
        for (int e = 0; e < 4; e++)
            cs[0][c4s*4+e][row] = (float)(int8_t)((unsigned)pc[it] >> (8*e));
        ws[0][c4s*4+0][row] = pw[it].x; ws[0][c4s*4+1][row] = pw[it].y;
        ws[0][c4s*4+2][row] = pw[it].z; ws[0][c4s*4+3][row] = pw[it].w;
    }
    __syncthreads();

    for (int kc = 0; kc < 24; kc++) {
        const int cur = kc & 1;
        if (kc + 1 < 24) {
            int k0 = (kc + 1) * 16;
            #pragma unroll
            for (int it = 0; it < 2; it++) {
                int row = r0s + it * 64;
                pc[it] = *(const int*)&g_ctx[(size_t)(m0 + row) * DMODEL + k0 + c4s * 4];
                pw[it] = *(const float4*)&wo[(size_t)(n0 + row) * DMODEL + k0 + c4s * 4];
            }
        }
        #pragma unroll
        for (int kk = 0; kk < 16; kk++) {
            ulonglong2 a01 = *(ulonglong2*)&cs[cur][kk][ty * 8];
            ulonglong2 a23 = *(ulonglong2*)&cs[cur][kk][ty * 8 + 4];
            float4 bA = *(float4*)&ws[cur][kk][tx * 4];
            float4 bB = *(float4*)&ws[cur][kk][64 + tx * 4];
            unsigned long long a[4] = {a01.x, a01.y, a23.x, a23.y};
            unsigned long long bd[8];
            bd[0] = pack2(bA.x, bA.x); bd[1] = pack2(bA.y, bA.y);
            bd[2] = pack2(bA.z, bA.z); bd[3] = pack2(bA.w, bA.w);
            bd[4] = pack2(bB.x, bB.x); bd[5] = pack2(bB.y, bB.y);
            bd[6] = pack2(bB.z, bB.z); bd[7] = pack2(bB.w, bB.w);
            #pragma unroll
            for (int i = 0; i < 4; i++)
                #pragma unroll
                for (int j = 0; j < 8; j++)
                    ffma2(acc[i][j], a[i], bd[j]);
        }
        if (kc + 1 < 24) {
            const int nb = (kc + 1) & 1;
            #pragma unroll
            for (int it = 0; it < 2; it++) {
                int row = r0s + it * 64;
                #pragma unroll
                for (int e = 0; e < 4; e++)
                    cs[nb][c4s*4+e][row] = (float)(int8_t)((unsigned)pc[it] >> (8*e));
                ws[nb][c4s*4+0][row] = pw[it].x; ws[nb][c4s*4+1][row] = pw[it].y;
                ws[nb][c4s*4+2][row] = pw[it].z; ws[nb][c4s*4+3][row] = pw[it].w;
            }
        }
        __syncthreads();
    }

    float bb[8];
    #pragma unroll
    for (int e = 0; e < 4; e++) bb[e] = bo[n0 + tx * 4 + e];
    #pragma unroll
    for (int e = 4; e < 8; e++) bb[e] = bo[n0 + 64 + tx * 4 + (e - 4)];

    #pragma unroll
    for (int mp = 0; mp < 4; mp++) {
        #pragma unroll
        for (int par = 0; par < 2; par++) {
            int m = m0 + ty * 8 + mp * 2 + par;
            float vals[8];
            #pragma unroll
            for (int j = 0; j < 8; j++) {
                float lo, hi; unpack2(acc[mp][j], lo, hi);
                float v = (par == 0) ? lo : hi;
                float r = floorf(((v + bb[j]) * 256.0f) * (1.0f / 128.0f));
                vals[j] = fminf(fmaxf(r, -128.0f), 127.0f);
            }
            *(float4*)&out[(size_t)m * DMODEL + n0 + tx * 4] =
                make_float4(vals[0], vals[1], vals[2], vals[3]);
            *(float4*)&out[(size_t)m * DMODEL + n0 + 64 + tx * 4] =
                make_float4(vals[4], vals[5], vals[6], vals[7]);
        }
    }
}

// ---------------------------------------------------------------------------
extern "C" void kernel_launch(void* const* d_in, const int* in_sizes, int n_in,
                              void* d_out, int out_size)
{
    const float* x  = (const float*)d_in[0];
    const float* wq = (const float*)d_in[1];
    const float* bq = (const float*)d_in[2];
    const float* wk = (const float*)d_in[3];
    const float* bk = (const float*)d_in[4];
    const float* wv = (const float*)d_in[5];
    const float* bv = (const float*)d_in[6];
    const float* wo = (const float*)d_in[7];
    const float* bo = (const float*)d_in[8];
    float* out = (float*)d_out;

    cudaFuncSetAttribute(attn_fused, cudaFuncAttributeMaxDynamicSharedMemorySize,
                         ATTN_SMEM_BYTES);

    proj_kernel<<<dim3(64, 3, 3), 256>>>(x, wq, bq, wk, bk, wv, bv);
    attn_fused<<<dim3(128, 24), 256, ATTN_SMEM_BYTES>>>();
    out_kernel<<<dim3(64, 3), 256>>>(wo, bo, out);
}

// round 16
// speedup vs baseline: 1.2362x; 1.2362x over previous
#include <cuda_runtime.h>
#include <cstdint>
#include <cstddef>

#define BATCH 4
#define SEQ 2048
#define DMODEL 384
#define NHEADS 6
#define HD 64
#define BH (BATCH*NHEADS)      /* 24 */

// ---------------- scratch (static device arrays; no cudaMalloc allowed) -------
__device__ __align__(16) int8_t g_Q  [(size_t)BH*SEQ*HD];        // [bh][n][d]
__device__ __align__(16) int8_t g_K  [(size_t)BH*SEQ*HD];        // [bh][n][d]
// V packed words: word (bh, nblk, d) = V[nblk*4 .. +3][d] bytes (packed along n)
__device__ __align__(16) int8_t g_Vp [(size_t)BH*(SEQ/4)*HD*4];  // [bh][nblk 512][d 64]
__device__ __align__(16) int8_t g_ctx[(size_t)BATCH*SEQ*DMODEL]; // [b][n][h*hd]

__device__ __forceinline__ int dp4a_us(unsigned a, int b, int c) {
    int d;
    asm("dp4a.u32.s32 %0, %1, %2, %3;" : "=r"(d) : "r"(a), "r"(b), "r"(c));
    return d;
}
__device__ __forceinline__ void ffma2(unsigned long long& d,
                                      unsigned long long a, unsigned long long b) {
    asm("fma.rn.f32x2 %0, %1, %2, %0;" : "+l"(d) : "l"(a), "l"(b));
}
__device__ __forceinline__ unsigned long long pack2(float lo, float hi) {
    unsigned long long p;
    asm("mov.b64 %0, {%1, %2};" : "=l"(p) : "f"(lo), "f"(hi));
    return p;
}
__device__ __forceinline__ void unpack2(unsigned long long p, float& lo, float& hi) {
    asm("mov.b64 {%0, %1}, %2;" : "=f"(lo), "=f"(hi) : "l"(p));
}
__device__ __forceinline__ int clamp_i8(int v) {
    return v < -128 ? -128 : (v > 127 ? 127 : v);
}
__device__ __forceinline__ unsigned pack_bytes(int v0, int v1, int v2, int v3) {
    return  ((unsigned)(unsigned char)(int8_t)v0)
          | (((unsigned)(unsigned char)(int8_t)v1) << 8)
          | (((unsigned)(unsigned char)(int8_t)v2) << 16)
          | (((unsigned)(unsigned char)(int8_t)v3) << 24);
}

// ---------------------------------------------------------------------------
// Kernel 1: QKV projection (f32x2 FMA, double-buffered, vectorized prefetch).
// Byte-identical to the verified 410.3us round (128us, rel_err 0).
// ---------------------------------------------------------------------------
__global__ void __launch_bounds__(256, 2) proj_kernel(
    const float* __restrict__ x,
    const float* __restrict__ wq, const float* __restrict__ bq,
    const float* __restrict__ wk, const float* __restrict__ bk,
    const float* __restrict__ wv, const float* __restrict__ bv)
{
    __shared__ float xs[2][16][132];   // [buf][kk][m]
    __shared__ float ws[2][16][132];   // [buf][kk][n]
    __shared__ int8_t vq[128][132];    // V transpose staging (z==2)

    const int z = blockIdx.z;
    const float* w    = (z == 0) ? wq : ((z == 1) ? wk : wv);
    const float* bias = (z == 0) ? bq : ((z == 1) ? bk : bv);
    const int m0 = blockIdx.x * 128;
    const int n0 = blockIdx.y * 128;
    const int tid = threadIdx.x, tx = tid & 15, ty = tid >> 4;
    const int r0s = tid >> 2;
    const int c4s = tid & 3;

    unsigned long long acc[4][8];
    #pragma unroll
    for (int i = 0; i < 4; i++)
        #pragma unroll
        for (int j = 0; j < 8; j++) acc[i][j] = 0ULL;

    float4 px[2], pw[2];
    #pragma unroll
    for (int it = 0; it < 2; it++) {
        int row = r0s + it * 64;
        px[it] = *(const float4*)&x[(size_t)(m0 + row) * DMODEL + c4s * 4];
        pw[it] = *(const float4*)&w[(size_t)(n0 + row) * DMODEL + c4s * 4];
    }
    #pragma unroll
    for (int it = 0; it < 2; it++) {
        int row = r0s + it * 64;
        xs[0][c4s*4+0][row] = px[it].x; xs[0][c4s*4+1][row] = px[it].y;
        xs[0][c4s*4+2][row] = px[it].z; xs[0][c4s*4+3][row] = px[it].w;
        ws[0][c4s*4+0][row] = pw[it].x; ws[0][c4s*4+1][row] = pw[it].y;
        ws[0][c4s*4+2][row] = pw[it].z; ws[0][c4s*4+3][row] = pw[it].w;
    }
    __syncthreads();

    for (int kc = 0; kc < 24; kc++) {
        const int cur = kc & 1;
        if (kc + 1 < 24) {
            int k0 = (kc + 1) * 16;
            #pragma unroll
            for (int it = 0; it < 2; it++) {
                int row = r0s + it * 64;
                px[it] = *(const float4*)&x[(size_t)(m0 + row) * DMODEL + k0 + c4s * 4];
                pw[it] = *(const float4*)&w[(size_t)(n0 + row) * DMODEL + k0 + c4s * 4];
            }
        }
        #pragma unroll
        for (int kk = 0; kk < 16; kk++) {
            ulonglong2 a01 = *(ulonglong2*)&xs[cur][kk][ty * 8];
            ulonglong2 a23 = *(ulonglong2*)&xs[cur][kk][ty * 8 + 4];
            float4 bA = *(float4*)&ws[cur][kk][tx * 4];
            float4 bB = *(float4*)&ws[cur][kk][64 + tx * 4];
            unsigned long long a[4] = {a01.x, a01.y, a23.x, a23.y};
            unsigned long long bd[8];
            bd[0] = pack2(bA.x, bA.x); bd[1] = pack2(bA.y, bA.y);
            bd[2] = pack2(bA.z, bA.z); bd[3] = pack2(bA.w, bA.w);
            bd[4] = pack2(bB.x, bB.x); bd[5] = pack2(bB.y, bB.y);
            bd[6] = pack2(bB.z, bB.z); bd[7] = pack2(bB.w, bB.w);
            #pragma unroll
            for (int i = 0; i < 4; i++)
                #pragma unroll
                for (int j = 0; j < 8; j++)
                    ffma2(acc[i][j], a[i], bd[j]);
        }
        if (kc + 1 < 24) {
            const int nb = (kc + 1) & 1;
            #pragma unroll
            for (int it = 0; it < 2; it++) {
                int row = r0s + it * 64;
                xs[nb][c4s*4+0][row] = px[it].x; xs[nb][c4s*4+1][row] = px[it].y;
                xs[nb][c4s*4+2][row] = px[it].z; xs[nb][c4s*4+3][row] = px[it].w;
                ws[nb][c4s*4+0][row] = pw[it].x; ws[nb][c4s*4+1][row] = pw[it].y;
                ws[nb][c4s*4+2][row] = pw[it].z; ws[nb][c4s*4+3][row] = pw[it].w;
            }
        }
        __syncthreads();
    }

    float bb[8];
    #pragma unroll
    for (int e = 0; e < 4; e++) bb[e] = bias[n0 + tx * 4 + e];
    #pragma unroll
    for (int e = 4; e < 8; e++) bb[e] = bias[n0 + 64 + tx * 4 + (e - 4)];

    if (z < 2) {
        int8_t* dst = (z == 0) ? g_Q : g_K;
        const int hA = n0 >> 6, hB = hA + 1;
        #pragma unroll
        for (int mp = 0; mp < 4; mp++) {
            #pragma unroll
            for (int par = 0; par < 2; par++) {
                int m = m0 + ty * 8 + mp * 2 + par;
                int b_ = m >> 11, n = m & 2047;
                unsigned wA = 0, wB = 0;
                #pragma unroll
                for (int j = 0; j < 8; j++) {
                    float lo, hi; unpack2(acc[mp][j], lo, hi);
                    float v = (par == 0) ? lo : hi;
                    float r = floorf(((v + bb[j]) * 16384.0f) * (1.0f / 256.0f));
                    r = fminf(fmaxf(r, -128.0f), 127.0f);
                    unsigned u = (unsigned)(unsigned char)(int8_t)(int)r;
                    if (j < 4) wA |= u << (8 * j);
                    else       wB |= u << (8 * (j - 4));
                }
                ((int*)dst)[((size_t)(b_ * NHEADS + hA) * SEQ + n) * 16 + tx] = (int)wA;
                ((int*)dst)[((size_t)(b_ * NHEADS + hB) * SEQ + n) * 16 + tx] = (int)wB;
            }
        }
    } else {
        #pragma unroll
        for (int mp = 0; mp < 4; mp++) {
            #pragma unroll
            for (int j = 0; j < 8; j++) {
                float lo, hi; unpack2(acc[mp][j], lo, hi);
                float r0 = floorf(((lo + bb[j]) * 16384.0f) * (1.0f / 256.0f));
                r0 = fminf(fmaxf(r0, -128.0f), 127.0f);
                float r1 = floorf(((hi + bb[j]) * 16384.0f) * (1.0f / 256.0f));
                r1 = fminf(fmaxf(r1, -128.0f), 127.0f);
                int col = (j < 4) ? (tx * 4 + j) : (64 + tx * 4 + (j - 4));
                vq[col][ty * 8 + mp * 2]     = (int8_t)(int)r0;
                vq[col][ty * 8 + mp * 2 + 1] = (int8_t)(int)r1;
            }
        }
        __syncthreads();
        int b_ = m0 >> 11;
        int nloc = m0 & 2047;
        #pragma unroll
        for (int it = 0; it < 16; it++) {
            int idx = tid + it * 256;
            int col = idx & 127;
            int j4  = idx >> 7;
            int word = *(int*)&vq[col][j4 * 4];
            int cg = n0 + col, h = cg >> 6, d = cg & 63;
            size_t nblk = (size_t)((nloc >> 2) + j4);
            ((int*)g_Vp)[((size_t)(b_ * NHEADS + h) * (SEQ/4) + nblk) * HD + d] = word;
        }
    }
}

// ---------------------------------------------------------------------------
// Kernel 2: fused attention, 256 threads, 16-q strips, 3 CTAs/SM.
// Exact structure of the verified 410.3us round; ONLY change: K staging loads
// vectorized to int4 (LDG.128), same smem placement and arithmetic.
// Phase 1: logits 16q x 256key tiles (dp4a, CF loads)
// Phase 2: ITA scan, 4-pass exact decomposition with pass-C early-out
// Phase 3: exact sparse attn@V (only es>0 chunks; V straight from L2)
// ---------------------------------------------------------------------------
#define QROWS 16
#define SW 516                                    /* padded S row (words) */
#define QSP 20                                    /* qs row pad */
#define KP 260                                    /* K tile row pad (256 keys) */
#define UB_INTS (16*KP)                           /* one K buffer: 4160 ints */
#define U_INTS (2*UB_INTS)                        /* 8320 ints (scan fits: 16*130) */
#define SCAN_P 130
#define ATTN_SMEM_INTS (QROWS*SW + 16*QSP + U_INTS + 48 + 512 + 32)
#define ATTN_SMEM_BYTES (ATTN_SMEM_INTS * 4)      /* ~70 KB -> 3 CTAs/SM */

extern __shared__ int smem_raw[];

__global__ void __launch_bounds__(256, 3) attn_fused()
{
    int* SM = smem_raw;
    unsigned* S = (unsigned*)SM;                  // [16][SW] logits words
    int* qs    = SM + QROWS * SW;                 // [16][QSP] transposed Q
    int* U     = qs + 16 * QSP;                   // K double-buffer / scan scratch
    int* gmaxs = U + U_INTS;                      // [16]
    int* invs  = gmaxs + QROWS;                   // [16]
    int* cnt   = invs + QROWS;                    // [16]
    unsigned char* lst = (unsigned char*)(cnt + QROWS);   // [16][128]

    const int bh = blockIdx.y;
    const int q0 = blockIdx.x * QROWS;
    const int tid = threadIdx.x;
    const int lane = tid & 31, warp = tid >> 5;   // 8 warps
    const int rg = warp & 3;                      // row group (rows rg*4..+3)
    const int kh = warp >> 2;                     // key half (0/1)

    const int* Qw = (const int*)g_Q + (size_t)bh * SEQ * (HD/4) + (size_t)q0 * (HD/4);
    const int4* Kw4 = (const int4*)((const int*)g_K + (size_t)bh * SEQ * (HD/4));

    // ---- Q transposed: qs[kk][qrow] (256 words) ----
    qs[(tid & 15) * QSP + (tid >> 4)] = Qw[(tid >> 4) * 16 + (tid & 15)];

    // ---- stage K tile 0 (256 keys x 16 words = 1024 int4), vectorized ----
    int4 pre4[4];
    #pragma unroll
    for (int it = 0; it < 4; it++) pre4[it] = Kw4[tid + it * 256];
    #pragma unroll
    for (int it = 0; it < 4; it++) {
        int idx = tid + it * 256;                 // 0..1023: key = idx>>2, c = idx&3
        int key = idx >> 2, c = idx & 3;
        U[(c * 4 + 0) * KP + key] = pre4[it].x;
        U[(c * 4 + 1) * KP + key] = pre4[it].y;
        U[(c * 4 + 2) * KP + key] = pre4[it].z;
        U[(c * 4 + 3) * KP + key] = pre4[it].w;
    }
    __syncthreads();

    // -------- Phase 1: logits, 8 tiles of 256 keys, single sync/tile --------
    for (int t = 0; t < 8; t++) {
        const int cur = t & 1;
        if (t + 1 < 8) {
            const int4* Kt4 = Kw4 + (size_t)(t + 1) * 1024;
            #pragma unroll
            for (int it = 0; it < 4; it++) pre4[it] = Kt4[tid + it * 256];
        }
        const int* kbc = U + cur * UB_INTS;
        int acc[4][4];
        #pragma unroll
        for (int i = 0; i < 4; i++)
            #pragma unroll
            for (int j = 0; j < 4; j++) acc[i][j] = 0;
        #pragma unroll
        for (int kk = 0; kk < 16; kk++) {
            int4 av = *(const int4*)&qs[kk * QSP + rg * 4];              // broadcast
            int4 bv = *(const int4*)&kbc[kk * KP + kh * 128 + lane * 4]; // CF stride 4
            int a[4] = {av.x, av.y, av.z, av.w};
            int b[4] = {bv.x, bv.y, bv.z, bv.w};
            #pragma unroll
            for (int i = 0; i < 4; i++)
                #pragma unroll
                for (int j = 0; j < 4; j++)
                    acc[i][j] = __dp4a(a[i], b[j], acc[i][j]);
        }
        #pragma unroll
        for (int i = 0; i < 4; i++) {
            unsigned w0 = pack_bytes(clamp_i8((acc[i][0]*5) >> 12), clamp_i8((acc[i][1]*5) >> 12),
                                     clamp_i8((acc[i][2]*5) >> 12), clamp_i8((acc[i][3]*5) >> 12));
            S[(rg * 4 + i) * SW + t * 64 + kh * 32 + lane] = w0;
        }
        if (t + 1 < 8) {
            const int nb = (t + 1) & 1;
            #pragma unroll
            for (int it = 0; it < 4; it++) {
                int idx = tid + it * 256;
                int key = idx >> 2, c = idx & 3;
                U[nb * UB_INTS + (c * 4 + 0) * KP + key] = pre4[it].x;
                U[nb * UB_INTS + (c * 4 + 1) * KP + key] = pre4[it].y;
                U[nb * UB_INTS + (c * 4 + 2) * KP + key] = pre4[it].z;
                U[nb * UB_INTS + (c * 4 + 3) * KP + key] = pre4[it].w;
            }
        }
        __syncthreads();
    }

    // -------- Phase 2: ITA scan, exact decomposition --------
    // Pass A: per-chunk maxima. 16 threads per row, interleaved chunks.
    {
        int row = tid >> 4, seg = tid & 15;
        const int* srow = (const int*)&S[row * SW];
        #pragma unroll
        for (int cc = 0; cc < 8; cc++) {
            int j = cc * 16 + seg;                // conflict-free
            int4 wv = *(const int4*)&srow[j * 4];
            int mw = __vmaxs4(__vmaxs4(wv.x, wv.y), __vmaxs4(wv.z, wv.w));
            int cmax = -128;
            #pragma unroll
            for (int b = 0; b < 4; b++) {
                int v = (int)(int8_t)((unsigned)mw >> (8 * b));
                cmax = max(cmax, v);
            }
            U[row * SCAN_P + j] = cmax;
        }
    }
    __syncthreads();
    // Pass B: running gmax per row; pack (gmax+128)<<24 | (cmax+128)<<16.
    if (tid < QROWS) {
        int g = -128;
        int* urow = U + tid * SCAN_P;
        for (int j = 0; j < 128; j++) {
            int c = urow[j];
            if (c > g) g = c;
            urow[j] = (int)(((unsigned)(g + 128) << 24) | ((unsigned)(c + 128) << 16));
        }
        gmaxs[tid] = g;
        cnt[tid] = 0;
    }
    __syncthreads();
    // Pass C: es per chunk, with early-out. es>0 <=> cmax >= gmax_j - 8.
    {
        int row = tid >> 4, seg = tid & 15;
        const int* srow = (const int*)&S[row * SW];
        int* urow = U + row * SCAN_P;
        #pragma unroll
        for (int cc = 0; cc < 8; cc++) {
            int j = cc * 16 + seg;
            unsigned pk = (unsigned)urow[j];
            int g = (int)(pk >> 24) - 128;
            int c = (int)((pk >> 16) & 0xFFu) - 128;
            if (c >= g - 8) {                      // relevant (es > 0); else es = 0 exactly
                int4 wv = *(const int4*)&srow[j * 4];
                int words[4] = {wv.x, wv.y, wv.z, wv.w};
                int es = 0;
                #pragma unroll
                for (int jw = 0; jw < 4; jw++) {
                    int wvv = words[jw];
                    #pragma unroll
                    for (int b = 0; b < 4; b++) {
                        int xv = (int)(int8_t)((unsigned)wvv >> (8 * b));
                        int df = g - xv;           // >= 0
                        es += (df < 9) ? (256 >> df) : 0;
                    }
                }
                urow[j] = (int)(pk | (unsigned)es);   // es <= 4096 fits 13 bits
                int pos = atomicAdd(&cnt[row], 1);
                lst[row * 128 + pos] = (unsigned char)j;
            }
        }
    }
    __syncthreads();
    // Pass D: exact sequential combine ps = (ps >> delta) + e
    if (tid < QROWS) {
        const int* urow = U + tid * SCAN_P;
        int ps = 0, gprev = -128;
        for (int j = 0; j < 128; j++) {
            unsigned pk = (unsigned)urow[j];
            int g = (int)(pk >> 24) - 128;
            int e = (int)(pk & 0x1FFFu);
            int sh = g - gprev;                   // >= 0
            ps = (sh < 31) ? (ps >> sh) : 0;
            ps += e;
            gprev = g;
        }
        invs[tid] = 65280 / ps;                   // exact == floor(65280.0/ps)
    }
    __syncthreads();

    // -------- Phase 3: EXACT SPARSE attn @ V --------
    // Warp handles 2 rows; lanes cover d (lane, lane+32). Skipped chunks are exact 0.
    {
        const int* Vg = (const int*)g_Vp + (size_t)bh * (SEQ/4) * HD;
        const int b_ = bh / NHEADS, h = bh % NHEADS;
        #pragma unroll
        for (int r = 0; r < 2; r++) {
            int row = warp * 2 + r;
            int n = cnt[row];
            int gm = gmaxs[row];
            unsigned inv = (unsigned)invs[row];
            int acc0 = 0, acc1 = 0;
            for (int ii = 0; ii < n; ii++) {
                int j = (int)lst[row * 128 + ii];                 // chunk id 0..127
                int4 lw = *(const int4*)&S[row * SW + j * 4];     // broadcast
                int lwa[4] = {lw.x, lw.y, lw.z, lw.w};
                #pragma unroll
                for (int kw = 0; kw < 4; kw++) {
                    unsigned xw = (unsigned)lwa[kw];
                    unsigned aw = 0;
                    #pragma unroll
                    for (int bb2 = 0; bb2 < 4; bb2++) {
                        int xv = (int)(int8_t)(xw >> (8 * bb2));
                        int df = gm - xv;
                        if (df > 31) df = 31;
                        aw |= (inv >> df) << (8 * bb2);
                    }
                    int base = (j * 4 + kw) * 64;                  // kword * HD
                    acc0 = dp4a_us(aw, Vg[base + lane],      acc0);
                    acc1 = dp4a_us(aw, Vg[base + 32 + lane], acc1);
                }
            }
            int q = q0 + row;
            int8_t* dst = g_ctx + ((size_t)(b_ * SEQ + q)) * DMODEL + h * HD;
            dst[lane]      = (int8_t)clamp_i8(acc0 >> 8);         // floor(acc/256)
            dst[32 + lane] = (int8_t)clamp_i8(acc1 >> 8);
        }
    }
}

// ---------------------------------------------------------------------------
// Kernel 3: out = requantize(ctx @ wo^T + bo, 256, 7), f32x2, double-buffered.
// Byte-identical to the verified 410.3us round.
// ---------------------------------------------------------------------------
__global__ void __launch_bounds__(256, 2) out_kernel(
    const float* __restrict__ wo, const float* __restrict__ bo,
    float* __restrict__ out)
{
    __shared__ float cs[2][16][132];
    __shared__ float ws[2][16][132];

    const int m0 = blockIdx.x * 128;
    const int n0 = blockIdx.y * 128;
    const int tid = threadIdx.x, tx = tid & 15, ty = tid >> 4;
    const int r0s = tid >> 2;
    const int c4s = tid & 3;

    unsigned long long acc[4][8];
    #pragma unroll
    for (int i = 0; i < 4; i++)
        #pragma unroll
        for (int j = 0; j < 8; j++) acc[i][j] = 0ULL;

    int pc[2]; float4 pw[2];
    #pragma unroll
    for (int it = 0; it < 2; it++) {
        int row = r0s + it * 64;
        pc[it] = *(const int*)&g_ctx[(size_t)(m0 + row) * DMODEL + c4s * 4];
        pw[it] = *(const float4*)&wo[(size_t)(n0 + row) * DMODEL + c4s * 4];
    }
    #pragma unroll
    for (int it = 0; it < 2; it++) {
        int row = r0s + it * 64;
        #pragma unroll
        for (int e = 0; e < 4; e++)
            cs[0][c4s*4+e][row] = (float)(int8_t)((unsigned)pc[it] >> (8*e));
        ws[0][c4s*4+0][row] = pw[it].x; ws[0][c4s*4+1][row] = pw[it].y;
        ws[0][c4s*4+2][row] = pw[it].z; ws[0][c4s*4+3][row] = pw[it].w;
    }
    __syncthreads();

    for (int kc = 0; kc < 24; kc++) {
        const int cur = kc & 1;
        if (kc + 1 < 24) {
            int k0 = (kc + 1) * 16;
            #pragma unroll
            for (int it = 0; it < 2; it++) {
                int row = r0s + it * 64;
                pc[it] = *(const int*)&g_ctx[(size_t)(m0 + row) * DMODEL + k0 + c4s * 4];
                pw[it] = *(const float4*)&wo[(size_t)(n0 + row) * DMODEL + k0 + c4s * 4];
            }
        }
        #pragma unroll
        for (int kk = 0; kk < 16; kk++) {
            ulonglong2 a01 = *(ulonglong2*)&cs[cur][kk][ty * 8];
            ulonglong2 a23 = *(ulonglong2*)&cs[cur][kk][ty * 8 + 4];
            float4 bA = *(float4*)&ws[cur][kk][tx * 4];
            float4 bB = *(float4*)&ws[cur][kk][64 + tx * 4];
            unsigned long long a[4] = {a01.x, a01.y, a23.x, a23.y};
            unsigned long long bd[8];
            bd[0] = pack2(bA.x, bA.x); bd[1] = pack2(bA.y, bA.y);
            bd[2] = pack2(bA.z, bA.z); bd[3] = pack2(bA.w, bA.w);
            bd[4] = pack2(bB.x, bB.x); bd[5] = pack2(bB.y, bB.y);
            bd[6] = pack2(bB.z, bB.z); bd[7] = pack2(bB.w, bB.w);
            #pragma unroll
            for (int i = 0; i < 4; i++)
                #pragma unroll
                for (int j = 0; j < 8; j++)
                    ffma2(acc[i][j], a[i], bd[j]);
        }
        if (kc + 1 < 24) {
            const int nb = (kc + 1) & 1;
            #pragma unroll
            for (int it = 0; it < 2; it++) {
                int row = r0s + it * 64;
                #pragma unroll
                for (int e = 0; e < 4; e++)
                    cs[nb][c4s*4+e][row] = (float)(int8_t)((unsigned)pc[it] >> (8*e));
                ws[nb][c4s*4+0][row] = pw[it].x; ws[nb][c4s*4+1][row] = pw[it].y;
                ws[nb][c4s*4+2][row] = pw[it].z; ws[nb][c4s*4+3][row] = pw[it].w;
            }
        }
        __syncthreads();
    }

    float bb[8];
    #pragma unroll
    for (int e = 0; e < 4; e++) bb[e] = bo[n0 + tx * 4 + e];
    #pragma unroll
    for (int e = 4; e < 8; e++) bb[e] = bo[n0 + 64 + tx * 4 + (e - 4)];

    #pragma unroll
    for (int mp = 0; mp < 4; mp++) {
        #pragma unroll
        for (int par = 0; par < 2; par++) {
            int m = m0 + ty * 8 + mp * 2 + par;
            float vals[8];
            #pragma unroll
            for (int j = 0; j < 8; j++) {
                float lo, hi; unpack2(acc[mp][j], lo, hi);
                float v = (par == 0) ? lo : hi;
                float r = floorf(((v + bb[j]) * 256.0f) * (1.0f / 128.0f));
                vals[j] = fminf(fmaxf(r, -128.0f), 127.0f);
            }
            *(float4*)&out[(size_t)m * DMODEL + n0 + tx * 4] =
                make_float4(vals[0], vals[1], vals[2], vals[3]);
            *(float4*)&out[(size_t)m * DMODEL + n0 + 64 + tx * 4] =
                make_float4(vals[4], vals[5], vals[6], vals[7]);
        }
    }
}

// ---------------------------------------------------------------------------
extern "C" void kernel_launch(void* const* d_in, const int* in_sizes, int n_in,
                              void* d_out, int out_size)
{
    const float* x  = (const float*)d_in[0];
    const float* wq = (const float*)d_in[1];
    const float* bq = (const float*)d_in[2];
    const float* wk = (const float*)d_in[3];
    const float* bk = (const float*)d_in[4];
    const float* wv = (const float*)d_in[5];
    const float* bv = (const float*)d_in[6];
    const float* wo = (const float*)d_in[7];
    const float* bo = (const float*)d_in[8];
    float* out = (float*)d_out;

    cudaFuncSetAttribute(attn_fused, cudaFuncAttributeMaxDynamicSharedMemorySize,
                         ATTN_SMEM_BYTES);

    proj_kernel<<<dim3(64, 3, 3), 256>>>(x, wq, bq, wk, bk, wv, bv);
    attn_fused<<<dim3(128, 24), 256, ATTN_SMEM_BYTES>>>();
    out_kernel<<<dim3(64, 3), 256>>>(wo, bo, out);
}